// round 1
// baseline (speedup 1.0000x reference)
#include <cuda_runtime.h>
#include <cuda_bf16.h>

#define FULL 0xffffffffu

namespace {
constexpr int NB   = 32;    // batch
constexpr int NP   = 32;    // n_patts
constexpr int DD   = 12;    // d_patts
constexpr int PP   = 32;    // l_patts (rows)
constexpr int LL   = 1024;  // l_seq (cols)
constexpr int LOUT = 32;
constexpr int WBLK = 128;        // columns per block
constexpr int NBLK = LL / WBLK;  // 8
constexpr float BIGV = 1e30f;
}

// One warp per (b, n). Row-scan DTW with w == 1 (RHO = 1.0 exactly), using the
// prefix-min reformulation:  cur[j] = S[j] + min_{k<=j}( m[k] - S[k-1] ),
// m[j] = min(D[i-1,j-1], D[i-1,j]),  S = prefix-sum of cost row.
__global__ void __launch_bounds__(32)
dtw_fused_kernel(const float* __restrict__ x,
                 const float* __restrict__ patts,
                 float* __restrict__ out)
{
    const int wid  = blockIdx.x;       // 0..1023
    const int b    = wid >> 5;
    const int n    = wid & 31;
    const int lane = threadIdx.x;

    // Per-lane pattern column: lane holds patts[n][d][lane]. Store -2*patt for the FMA.
    float prow[DD];
    float p2 = 0.0f;
    {
        const float* pp = patts + n * (DD * PP) + lane;
        #pragma unroll
        for (int d = 0; d < DD; ++d) {
            float v = pp[d * PP];
            p2 = fmaf(v, v, p2);
            prow[d] = -2.0f * v;
        }
    }

    const float* xb   = x + b * (DD * LL);
    float*       outb = out + ((b * NP + n) * PP) * LOUT;

    float oldC = BIGV;   // lane i holds D[i][j0-1] (carry from previous column block)
    float Dp[4];         // previous row, this block (blocked: lane holds cols j0+4*lane+k)

    for (int blk = 0; blk < NBLK; ++blk) {
        const int j0 = blk * WBLK;

        // Load x chunk for this column block (reused by all 32 rows) + x2.
        float xr[DD][4];
        float x2[4] = {0.f, 0.f, 0.f, 0.f};
        #pragma unroll
        for (int d = 0; d < DD; ++d) {
            float4 v = *reinterpret_cast<const float4*>(xb + d * LL + j0 + 4 * lane);
            xr[d][0] = v.x; xr[d][1] = v.y; xr[d][2] = v.z; xr[d][3] = v.w;
            #pragma unroll
            for (int k = 0; k < 4; ++k) x2[k] = fmaf(xr[d][k], xr[d][k], x2[k]);
        }

        float newC = BIGV;  // lane i will hold D[i][j0+WBLK-1]

        for (int i = 0; i < PP; ++i) {
            // ---- broadcasts for row i ----
            float p2b = __shfl_sync(FULL, p2, i);
            float pb[DD];
            #pragma unroll
            for (int d = 0; d < DD; ++d) pb[d] = __shfl_sync(FULL, prow[d], i);
            float bl = __shfl_sync(FULL, oldC, i);                 // D[i][j0-1]
            float bm = __shfl_sync(FULL, oldC, (i - 1) & 31);      // D[i-1][j0-1]
            if (i == 0) { bm = BIGV; if (blk == 0) bl = 0.0f; }    // D[0,0] seed

            // ---- cost row (128 cells): c = p2 + x2 - 2*sum_d patt*x ----
            float c0 = p2b + x2[0], c1 = p2b + x2[1], c2 = p2b + x2[2], c3 = p2b + x2[3];
            #pragma unroll
            for (int d = 0; d < DD; ++d) {
                c0 = fmaf(pb[d], xr[d][0], c0);
                c1 = fmaf(pb[d], xr[d][1], c1);
                c2 = fmaf(pb[d], xr[d][2], c2);
                c3 = fmaf(pb[d], xr[d][3], c3);
            }

            // ---- local prefix sum, then warp inclusive sum scan of lane totals ----
            float s0 = c0, s1 = s0 + c1, s2 = s1 + c2, s3 = s2 + c3;
            float tot = s3;
            #pragma unroll
            for (int o = 1; o < 32; o <<= 1) {
                float u = __shfl_up_sync(FULL, tot, o);
                if (lane >= o) tot += u;
            }
            const float excl = tot - s3;   // exclusive warp prefix (S before this lane)

            // ---- m = min(up-left, up); t = m - S[j-1] ----
            float t0, t1, t2, t3;
            {
                float shin = __shfl_up_sync(FULL, Dp[3], 1);  // prev lane's last Dp
                if (i == 0) {
                    t0 = t1 = t2 = t3 = BIGV;                 // no row above
                } else {
                    float mprev = (lane == 0) ? bm : shin;
                    t0 = fminf(mprev, Dp[0]) - excl;
                    t1 = fminf(Dp[0], Dp[1]) - (excl + s0);
                    t2 = fminf(Dp[1], Dp[2]) - (excl + s1);
                    t3 = fminf(Dp[2], Dp[3]) - (excl + s2);
                }
            }

            // ---- prefix-min (left-entry carry bl injected at global position -1) ----
            float q0 = (lane == 0) ? fminf(bl, t0) : t0;
            float q1 = fminf(q0, t1);
            float q2 = fminf(q1, t2);
            float q3 = fminf(q2, t3);
            float mt = q3;
            #pragma unroll
            for (int o = 1; o < 32; o <<= 1) {
                // shfl_up returns own value when out of range; min(v,v)=v is harmless.
                mt = fminf(mt, __shfl_up_sync(FULL, mt, o));
            }
            float eprev = __shfl_up_sync(FULL, mt, 1);   // exclusive min over lanes < lane
            if (lane == 0) eprev = BIGV;

            // ---- cur = S + prefix-min ----
            float cur0 = (excl + s0) + fminf(eprev, q0);
            float cur1 = (excl + s1) + fminf(eprev, q1);
            float cur2 = (excl + s2) + fminf(eprev, q2);
            float cur3 = (excl + s3) + fminf(eprev, q3);

            // ---- carry: D[i][j0+127] lives in lane 31 reg 3 ----
            float last = __shfl_sync(FULL, cur3, 31);
            if (lane == i) newC = last;

            // ---- output tail: cols 992..1023 == lanes 24..31 of last block ----
            if (blk == NBLK - 1 && lane >= 24) {
                float4 o4 = make_float4(cur0, cur1, cur2, cur3);
                *reinterpret_cast<float4*>(outb + i * LOUT + (lane - 24) * 4) = o4;
            }

            Dp[0] = cur0; Dp[1] = cur1; Dp[2] = cur2; Dp[3] = cur3;
        }
        oldC = newC;
    }
}

extern "C" void kernel_launch(void* const* d_in, const int* in_sizes, int n_in,
                              void* d_out, int out_size) {
    const float* x     = (const float*)d_in[0];   // [32, 12, 1024]
    const float* patts = (const float*)d_in[1];   // [32, 12, 32]
    float* out = (float*)d_out;                   // [32, 32, 32, 32]
    (void)in_sizes; (void)n_in; (void)out_size;
    dtw_fused_kernel<<<NB * NP, 32>>>(x, patts, out);
}

// round 2
// speedup vs baseline: 1.4006x; 1.4006x over previous
#include <cuda_runtime.h>
#include <cuda_bf16.h>

#define FULL 0xffffffffu

namespace {
constexpr int NB   = 32;
constexpr int NP   = 32;
constexpr int DD   = 12;
constexpr int PP   = 32;
constexpr int LL   = 1024;
constexpr int LOUT = 32;
constexpr int CPL  = 8;            // cols per lane
constexpr int WBLK = 32 * CPL;     // 256 cols per block
constexpr int NBLK = LL / WBLK;    // 4
constexpr float BIGV = 1e30f;
}

// One warp per (b, n). w == 1 (RHO = 1.0), prefix-min reformulation:
//   cur[j] = S[j] + min_{k<=j}( m[k] - S[k-1] ),  m[j] = min(D[i-1,j-1], D[i-1,j])
// Row loop is software-pipelined: cost+sum-scan of row i+1 is computed in the
// same loop body as the DP min-scan of row i, so the two shfl chains interleave.
__global__ void __launch_bounds__(32)
dtw_fused_kernel(const float* __restrict__ x,
                 const float* __restrict__ patts,
                 float* __restrict__ out)
{
    const int wid  = blockIdx.x;
    const int b    = wid >> 5;
    const int n    = wid & 31;
    const int lane = threadIdx.x;

    // lane holds patts[n][d][lane]; store -2*p for the FMA form of sqdist.
    float prow[DD];
    float p2 = 0.0f;
    {
        const float* pp = patts + n * (DD * PP) + lane;
        #pragma unroll
        for (int d = 0; d < DD; ++d) {
            float v = pp[d * PP];
            p2 = fmaf(v, v, p2);
            prow[d] = -2.0f * v;
        }
    }

    const float* xb   = x + b * (DD * LL);
    float*       outb = out + ((b * NP + n) * PP) * LOUT;

    float oldC = BIGV;    // lane i: D[i][j0-1] carry from previous column block
    float Dp[CPL];        // previous row of current block (lane holds 8 consecutive cols)

    for (int blk = 0; blk < NBLK; ++blk) {
        const int j0 = blk * WBLK;

        // x chunk for this block, reused by all 32 rows.
        float xr[DD][CPL];
        float x2[CPL] = {0.f, 0.f, 0.f, 0.f, 0.f, 0.f, 0.f, 0.f};
        #pragma unroll
        for (int d = 0; d < DD; ++d) {
            const float* px = xb + d * LL + j0 + CPL * lane;
            float4 v0 = *reinterpret_cast<const float4*>(px);
            float4 v1 = *reinterpret_cast<const float4*>(px + 4);
            xr[d][0] = v0.x; xr[d][1] = v0.y; xr[d][2] = v0.z; xr[d][3] = v0.w;
            xr[d][4] = v1.x; xr[d][5] = v1.y; xr[d][6] = v1.z; xr[d][7] = v1.w;
            #pragma unroll
            for (int k = 0; k < CPL; ++k) x2[k] = fmaf(xr[d][k], xr[d][k], x2[k]);
        }

        float newC = BIGV;

        // cost row + local inclusive prefix + warp-exclusive sum for row i
        auto costscan = [&](int i, float s[CPL], float& excl) {
            float p2b = __shfl_sync(FULL, p2, i);
            float c[CPL];
            #pragma unroll
            for (int k = 0; k < CPL; ++k) c[k] = p2b + x2[k];
            #pragma unroll
            for (int d = 0; d < DD; ++d) {
                float pb = __shfl_sync(FULL, prow[d], i);
                #pragma unroll
                for (int k = 0; k < CPL; ++k) c[k] = fmaf(pb, xr[d][k], c[k]);
            }
            s[0] = c[0];
            #pragma unroll
            for (int k = 1; k < CPL; ++k) s[k] = s[k - 1] + c[k];
            float tot = s[CPL - 1];
            #pragma unroll
            for (int o = 1; o < 32; o <<= 1) {
                float u = __shfl_up_sync(FULL, tot, o);
                if (lane >= o) tot += u;
            }
            excl = tot - s[CPL - 1];
        };

        float sC[CPL], eC;
        costscan(0, sC, eC);

        for (int i = 0; i < PP; ++i) {
            // ---- pipeline: next row's cost + sum-scan (independent of DP chain) ----
            float sN[CPL], eN;
            if (i + 1 < PP) costscan(i + 1, sN, eN);

            // ---- DP min-scan for row i ----
            float bl = __shfl_sync(FULL, oldC, i);              // D[i][j0-1]
            float bm = __shfl_sync(FULL, oldC, (i - 1) & 31);   // D[i-1][j0-1]
            if (i == 0) { bm = BIGV; if (blk == 0) bl = 0.0f; }

            float t[CPL];
            float shin = __shfl_up_sync(FULL, Dp[CPL - 1], 1);
            if (i == 0) {
                #pragma unroll
                for (int k = 0; k < CPL; ++k) t[k] = BIGV;
            } else {
                float mprev = (lane == 0) ? bm : shin;
                t[0] = fminf(mprev, Dp[0]) - eC;
                #pragma unroll
                for (int k = 1; k < CPL; ++k)
                    t[k] = fminf(Dp[k - 1], Dp[k]) - (eC + sC[k - 1]);
            }

            float q[CPL];
            q[0] = (lane == 0) ? fminf(bl, t[0]) : t[0];
            #pragma unroll
            for (int k = 1; k < CPL; ++k) q[k] = fminf(q[k - 1], t[k]);

            float mt = q[CPL - 1];
            #pragma unroll
            for (int o = 1; o < 32; o <<= 1)
                mt = fminf(mt, __shfl_up_sync(FULL, mt, o));   // self-min OOR is a no-op
            float eprev = __shfl_up_sync(FULL, mt, 1);
            if (lane == 0) eprev = BIGV;

            float cur[CPL];
            #pragma unroll
            for (int k = 0; k < CPL; ++k)
                cur[k] = (eC + sC[k]) + fminf(eprev, q[k]);

            // carry D[i][j0+255] (lane 31, reg 7) into newC lane i
            float last = __shfl_sync(FULL, cur[CPL - 1], 31);
            if (lane == i) newC = last;

            // output cols 992..1023 = lanes 28..31 of the last block
            if (blk == NBLK - 1 && lane >= 28) {
                float* po = outb + i * LOUT + (lane - 28) * CPL;
                *reinterpret_cast<float4*>(po)     = make_float4(cur[0], cur[1], cur[2], cur[3]);
                *reinterpret_cast<float4*>(po + 4) = make_float4(cur[4], cur[5], cur[6], cur[7]);
            }

            #pragma unroll
            for (int k = 0; k < CPL; ++k) Dp[k] = cur[k];
            #pragma unroll
            for (int k = 0; k < CPL; ++k) sC[k] = sN[k];
            eC = eN;
        }
        oldC = newC;
    }
}

extern "C" void kernel_launch(void* const* d_in, const int* in_sizes, int n_in,
                              void* d_out, int out_size) {
    const float* x     = (const float*)d_in[0];   // [32, 12, 1024]
    const float* patts = (const float*)d_in[1];   // [32, 12, 32]
    float* out = (float*)d_out;                   // [32, 32, 32, 32]
    (void)in_sizes; (void)n_in; (void)out_size;
    dtw_fused_kernel<<<NB * NP, 32>>>(x, patts, out);
}

// round 3
// speedup vs baseline: 1.4952x; 1.0676x over previous
#include <cuda_runtime.h>
#include <cuda_bf16.h>

#define FULL 0xffffffffu

namespace {
constexpr int NB   = 32;
constexpr int NP   = 32;
constexpr int DD   = 12;
constexpr int PP   = 32;
constexpr int LL   = 1024;
constexpr int LOUT = 32;
constexpr int CPL  = 8;            // cols per lane
constexpr int WBLK = 32 * CPL;     // 256 cols per warp
constexpr int NBLK = LL / WBLK;    // 4 warps per (b,n)
constexpr float BIGV = 1e30f;
}

// One CTA (4 warps) per (b, n). Warp w owns column block w. Diagonal wavefront:
// at step t, warp w computes DP row i = t - w. The only cross-warp value is the
// last-column carry D[i][j0-1], passed through smem with one barrier per step.
// Per-row math: w == 1 (RHO = 1.0) prefix-min reformulation,
//   cur[j] = S[j] + min_{k<=j}( m[k] - S[k-1] ),  m[j] = min(D[i-1,j-1], D[i-1,j])
__global__ void __launch_bounds__(128, 3)
dtw_fused_kernel(const float* __restrict__ x,
                 const float* __restrict__ patts,
                 float* __restrict__ out)
{
    const int gid  = blockIdx.x;        // 0..1023
    const int b    = gid >> 5;
    const int n    = gid & 31;
    const int w    = threadIdx.x >> 5;  // column block 0..3
    const int lane = threadIdx.x & 31;

    __shared__ float carry[NBLK][PP];   // carry[w][i] = D[i][(w+1)*WBLK - 1]

    // lane holds patts[n][d][lane]; store -2*p for the FMA form of sqdist.
    float prow[DD];
    float p2 = 0.0f;
    {
        const float* pp = patts + n * (DD * PP) + lane;
        #pragma unroll
        for (int d = 0; d < DD; ++d) {
            float v = pp[d * PP];
            p2 = fmaf(v, v, p2);
            prow[d] = -2.0f * v;
        }
    }

    // x chunk for this warp's column block, reused by all 32 rows.
    const float* xb = x + b * (DD * LL);
    const int j0 = w * WBLK;
    float xr[DD][CPL];
    float x2[CPL] = {0.f, 0.f, 0.f, 0.f, 0.f, 0.f, 0.f, 0.f};
    #pragma unroll
    for (int d = 0; d < DD; ++d) {
        const float* px = xb + d * LL + j0 + CPL * lane;
        float4 v0 = *reinterpret_cast<const float4*>(px);
        float4 v1 = *reinterpret_cast<const float4*>(px + 4);
        xr[d][0] = v0.x; xr[d][1] = v0.y; xr[d][2] = v0.z; xr[d][3] = v0.w;
        xr[d][4] = v1.x; xr[d][5] = v1.y; xr[d][6] = v1.z; xr[d][7] = v1.w;
        #pragma unroll
        for (int k = 0; k < CPL; ++k) x2[k] = fmaf(xr[d][k], xr[d][k], x2[k]);
    }

    float* outb = out + ((b * NP + n) * PP) * LOUT;

    float Dp[CPL];  // previous DP row for this warp's block

    #pragma unroll 1
    for (int t = 0; t < PP + NBLK - 1; ++t) {
        const int i = t - w;
        if (i >= 0 && i < PP) {
            // ---- cost row + local prefix + warp-exclusive sum ----
            float p2b = __shfl_sync(FULL, p2, i);
            float c[CPL];
            #pragma unroll
            for (int k = 0; k < CPL; ++k) c[k] = p2b + x2[k];
            #pragma unroll
            for (int d = 0; d < DD; ++d) {
                float pb = __shfl_sync(FULL, prow[d], i);
                #pragma unroll
                for (int k = 0; k < CPL; ++k) c[k] = fmaf(pb, xr[d][k], c[k]);
            }
            float s[CPL];
            s[0] = c[0];
            #pragma unroll
            for (int k = 1; k < CPL; ++k) s[k] = s[k - 1] + c[k];
            float tot = s[CPL - 1];
            #pragma unroll
            for (int o = 1; o < 32; o <<= 1) {
                float u = __shfl_up_sync(FULL, tot, o);
                if (lane >= o) tot += u;
            }
            const float eC = tot - s[CPL - 1];  // exclusive sum prefix

            // ---- boundary carries from the warp to the left ----
            float bl, bm;  // D[i][j0-1], D[i-1][j0-1]
            if (w == 0) {
                bl = (i == 0) ? 0.0f : BIGV;   // D[0,0] seed; col -1 otherwise OOR
                bm = BIGV;
            } else {
                bl = carry[w - 1][i];
                bm = (i > 0) ? carry[w - 1][i - 1] : BIGV;
            }

            // ---- t[k] = min(up-left, up) - S[j-1] ----
            float tt[CPL];
            float shin = __shfl_up_sync(FULL, Dp[CPL - 1], 1);
            if (i == 0) {
                #pragma unroll
                for (int k = 0; k < CPL; ++k) tt[k] = BIGV;
            } else {
                float mprev = (lane == 0) ? bm : shin;
                tt[0] = fminf(mprev, Dp[0]) - eC;
                #pragma unroll
                for (int k = 1; k < CPL; ++k)
                    tt[k] = fminf(Dp[k - 1], Dp[k]) - (eC + s[k - 1]);
            }

            // ---- prefix-min with left-entry bl injected at position -1 ----
            float q[CPL];
            q[0] = (lane == 0) ? fminf(bl, tt[0]) : tt[0];
            #pragma unroll
            for (int k = 1; k < CPL; ++k) q[k] = fminf(q[k - 1], tt[k]);

            float mt = q[CPL - 1];
            #pragma unroll
            for (int o = 1; o < 32; o <<= 1)
                mt = fminf(mt, __shfl_up_sync(FULL, mt, o));  // OOR self-min: no-op
            float eprev = __shfl_up_sync(FULL, mt, 1);
            if (lane == 0) eprev = BIGV;

            float cur[CPL];
            #pragma unroll
            for (int k = 0; k < CPL; ++k)
                cur[k] = (eC + s[k]) + fminf(eprev, q[k]);

            // ---- publish carry for the warp to the right ----
            if (w < NBLK - 1 && lane == 31) carry[w][i] = cur[CPL - 1];

            // ---- output: cols 992..1023 = lanes 28..31 of last warp ----
            if (w == NBLK - 1 && lane >= 28) {
                float* po = outb + i * LOUT + (lane - 28) * CPL;
                *reinterpret_cast<float4*>(po)     = make_float4(cur[0], cur[1], cur[2], cur[3]);
                *reinterpret_cast<float4*>(po + 4) = make_float4(cur[4], cur[5], cur[6], cur[7]);
            }

            #pragma unroll
            for (int k = 0; k < CPL; ++k) Dp[k] = cur[k];
        }
        __syncthreads();
    }
}

extern "C" void kernel_launch(void* const* d_in, const int* in_sizes, int n_in,
                              void* d_out, int out_size) {
    const float* x     = (const float*)d_in[0];   // [32, 12, 1024]
    const float* patts = (const float*)d_in[1];   // [32, 12, 32]
    float* out = (float*)d_out;                   // [32, 32, 32, 32]
    (void)in_sizes; (void)n_in; (void)out_size;
    dtw_fused_kernel<<<NB * NP, 128>>>(x, patts, out);
}